// round 15
// baseline (speedup 1.0000x reference)
#include <cuda_runtime.h>
#include <cuda_bf16.h>
#include <cuda_fp16.h>
#include <cstdint>

typedef unsigned long long ull;

#define BB 128
#define SS 512
#define HH 128
#define EPSM 5.9604644775390625e-08f   // 2^-24, exact fp16 subnormal

// -------- static device scratch --------
static __device__ unsigned char g_code[(size_t)BB * SS * SS];
static __device__ float g_hbuf1[(size_t)BB * SS * HH];
static __device__ uint32_t g_hhi[2][(size_t)BB * SS * HH / 2];  // f16x2 pairs
static __device__ float g_sav[2][BB * SS];
static __device__ float g_sbv[2][BB * SS];

// ---------------- fast math ----------------
__device__ __forceinline__ float tanha(float x) {
    float r; asm("tanh.approx.f32 %0,%1;" : "=f"(r) : "f"(x)); return r;
}
__device__ __forceinline__ float ex2a(float x) {
    float r; asm("ex2.approx.f32 %0,%1;" : "=f"(r) : "f"(x)); return r;
}
__device__ __forceinline__ uint32_t f2h2(float hi, float lo) {
    uint32_t r; asm("cvt.rn.f16x2.f32 %0,%1,%2;" : "=r"(r) : "f"(hi), "f"(lo)); return r;
}

// ---------------- mma / ldsm / cp.async / named barriers ----------------
__device__ __forceinline__ void ldsm_x4(uint32_t r[4], uint32_t addr) {
    asm volatile("ldmatrix.sync.aligned.m8n8.x4.shared.b16 {%0,%1,%2,%3}, [%4];"
        : "=r"(r[0]), "=r"(r[1]), "=r"(r[2]), "=r"(r[3]) : "r"(addr));
}
__device__ __forceinline__ void ldsm_x4_t(uint32_t r[4], uint32_t addr) {
    asm volatile("ldmatrix.sync.aligned.m8n8.x4.trans.shared.b16 {%0,%1,%2,%3}, [%4];"
        : "=r"(r[0]), "=r"(r[1]), "=r"(r[2]), "=r"(r[3]) : "r"(addr));
}
__device__ __forceinline__ void mma16816h(float acc[4], const uint32_t a[4],
                                          uint32_t b0, uint32_t b1) {
    asm volatile(
        "mma.sync.aligned.m16n8k16.row.col.f32.f16.f16.f32 "
        "{%0,%1,%2,%3}, {%4,%5,%6,%7}, {%8,%9}, {%0,%1,%2,%3};\n"
        : "+f"(acc[0]), "+f"(acc[1]), "+f"(acc[2]), "+f"(acc[3])
        : "r"(a[0]), "r"(a[1]), "r"(a[2]), "r"(a[3]), "r"(b0), "r"(b1));
}
__device__ __forceinline__ void cp16(uint32_t dst, const void* src) {
    asm volatile("cp.async.cg.shared.global [%0], [%1], 16;" :: "r"(dst), "l"(src));
}
#define CP_COMMIT() asm volatile("cp.async.commit_group;" ::: "memory")
#define CP_WAIT0()  asm volatile("cp.async.wait_group 0;" ::: "memory")
#define BAR_SYNC(id)    asm volatile("bar.sync %0, 256;"   :: "r"(id) : "memory")
#define BAR_ARRIVE(id)  asm volatile("bar.arrive %0, 256;" :: "r"(id) : "memory")
#define BAR_SYNC_C(id)  asm volatile("bar.sync %0, 128;"   :: "r"(id) : "memory")

// ---------------------------------------------------------------
// Kernel 1: symmetric pack, 64x64 pair-tiles, float4 loads
// ---------------------------------------------------------------
#define NT64 (SS / 64)
#define NPAIR64 (NT64 * (NT64 + 1) / 2)

__global__ __launch_bounds__(256) void pack_code_kernel(const float* __restrict__ adj) {
    __shared__ float tA[64][65], tB[64][65];
    const int b = blockIdx.z;
    int rem = blockIdx.x;
    int It = 0;
    while (rem >= NT64 - It) { rem -= NT64 - It; It++; }
    const int I = It * 64;
    const int J = (It + rem) * 64;
    const int tid = threadIdx.x;
    const float* A = adj + (size_t)b * SS * SS;

    #pragma unroll
    for (int t = 0; t < 4; t++) {
        const int idx = t * 256 + tid;
        const int r = idx >> 4, c4 = idx & 15;
        const float4 va = *(const float4*)(A + (size_t)(I + r) * SS + J + c4 * 4);
        const float4 vb = *(const float4*)(A + (size_t)(J + r) * SS + I + c4 * 4);
        tA[r][c4 * 4 + 0] = va.x; tA[r][c4 * 4 + 1] = va.y;
        tA[r][c4 * 4 + 2] = va.z; tA[r][c4 * 4 + 3] = va.w;
        tB[r][c4 * 4 + 0] = vb.x; tB[r][c4 * 4 + 1] = vb.y;
        tB[r][c4 * 4 + 2] = vb.z; tB[r][c4 * 4 + 3] = vb.w;
    }
    __syncthreads();

    #pragma unroll
    for (int t = 0; t < 4; t++) {
        const int idx = t * 256 + tid;
        const int r = idx >> 4, c4 = idx & 15;
        unsigned char e0[4], e1[4];
        #pragma unroll
        for (int e = 0; e < 4; e++) {
            const int c = c4 * 4 + e;
            e0[e] = (tA[r][c] == 1.0f ? 1u : 0u) | (tB[c][r] == 1.0f ? 2u : 0u);
            e1[e] = (tB[r][c] == 1.0f ? 1u : 0u) | (tA[c][r] == 1.0f ? 2u : 0u);
        }
        *(uchar4*)(g_code + ((size_t)b * SS + I + r) * SS + J + c4 * 4) =
            make_uchar4(e0[0], e0[1], e0[2], e0[3]);
        *(uchar4*)(g_code + ((size_t)b * SS + J + r) * SS + I + c4 * 4) =
            make_uchar4(e1[0], e1[1], e1[2], e1[3]);
    }
}

// ---------------------------------------------------------------
// Kernel 2: sa/sb projections + single-fp16 pack of input hidden
// ---------------------------------------------------------------
__global__ void sasb_split_kernel(const float* __restrict__ hin,
                                  const float* __restrict__ w1,
                                  const float* __restrict__ w2,
                                  const float* __restrict__ bias_ptr,
                                  uint32_t* __restrict__ hi_out,
                                  float* __restrict__ sa_out,
                                  float* __restrict__ sb_out) {
    const int tid  = threadIdx.x;
    const int lane = tid & 31;
    const int row  = blockIdx.x * 8 + (tid >> 5);
    if (row >= BB * SS) return;

    const float4 hv  = reinterpret_cast<const float4*>(hin)[(size_t)row * 32 + lane];
    const float4 w1v = reinterpret_cast<const float4*>(w1)[lane];
    const float4 w2v = reinterpret_cast<const float4*>(w2)[lane];

    reinterpret_cast<uint2*>(hi_out)[(size_t)row * 32 + lane] =
        make_uint2(f2h2(hv.y, hv.x), f2h2(hv.w, hv.z));

    float d1 = hv.x * w1v.x + hv.y * w1v.y + hv.z * w1v.z + hv.w * w1v.w;
    float d2 = hv.x * w2v.x + hv.y * w2v.y + hv.z * w2v.z + hv.w * w2v.w;
    #pragma unroll
    for (int off = 16; off > 0; off >>= 1) {
        d1 += __shfl_xor_sync(0xFFFFFFFFu, d1, off);
        d2 += __shfl_xor_sync(0xFFFFFFFFu, d2, off);
    }
    if (lane == 0) {
        sa_out[row] = d1 + bias_ptr[0];
        sb_out[row] = d2;
    }
}

// ---------------------------------------------------------------
// score quad (MUFU) -> single fp16 P
// ---------------------------------------------------------------
#define HLOG2E 0.721347520444f

__device__ __forceinline__ float quad4(uint32_t c4, const float4 sa4, const float4 sb4,
                                       const float sai, const float sbi,
                                       uint32_t& h01, uint32_t& h23) {
    float t1[4], t2[4];
    t1[0] = tanha(sai + sb4.x);  t1[1] = tanha(sai + sb4.y);
    t1[2] = tanha(sai + sb4.z);  t1[3] = tanha(sai + sb4.w);
    t2[0] = tanha(sa4.x + sbi);  t2[1] = tanha(sa4.y + sbi);
    t2[2] = tanha(sa4.z + sbi);  t2[3] = tanha(sa4.w + sbi);
    float e[4]; float es = 0.0f;
    #pragma unroll
    for (int k = 0; k < 4; k++) {
        const uint32_t c = (c4 >> (8 * k)) & 0xFFu;
        const float f1 = (c & 1u) ? t1[k] : 0.0f;
        const float f2 = (c & 2u) ? t2[k] : 0.0f;
        const float ev = ex2a((f1 + f2) * HLOG2E);
        e[k] = c ? ev : EPSM;
        es += e[k];
    }
    h01 = f2h2(e[1], e[0]);
    h23 = f2h2(e[3], e[2]);
    return es;
}

// ---------------------------------------------------------------
// Kernel 3: WARP-SPECIALIZED fused, 32 rows/block, 256 thr, occ 3.
// Warps 0-3: MMA consumers (2 M-tiles x 2 N-halves).
// Warps 4-7: E producers (4 thr/row) + H cp.async.
// smem 48512 B; __launch_bounds__(256,3) (85 regs).
// ---------------------------------------------------------------
#define OFF_SA   0
#define OFF_SB   2048
#define OFF_RS   4096
#define OFF_RED  4224
#define OFF_W1   4480
#define OFF_W2   4992
#define OFF_P    5504
#define P_BUFSZ  4096
#define OFF_H    13696
#define H_BUFSZ  17408
#define SMEM_TOTAL 48512
#define LDHB 272

__global__ __launch_bounds__(256, 3)
void fused_layer_kernel(const uint32_t* __restrict__ hhi_in,
                        const float* __restrict__ sa_in,
                        const float* __restrict__ sb_in,
                        float* __restrict__ hout,
                        uint32_t* __restrict__ hhi_out,
                        float* __restrict__ sa_out,
                        float* __restrict__ sb_out,
                        const float* __restrict__ w1,
                        const float* __restrict__ w2,
                        const float* __restrict__ bias_ptr,
                        int mode) {
    extern __shared__ char smem[];
    float* s_sa   = (float*)(smem + OFF_SA);
    float* s_sb   = (float*)(smem + OFF_SB);
    float* s_rsum = (float*)(smem + OFF_RS);
    float* s_red  = (float*)(smem + OFF_RED);
    float* s_w1   = (float*)(smem + OFF_W1);
    float* s_w2   = (float*)(smem + OFF_W2);
    const uint32_t su = (uint32_t)__cvta_generic_to_shared(smem);

    const int b    = blockIdx.y;
    const int i0   = blockIdx.x * 32;
    const int tid  = threadIdx.x;
    const int lane = tid & 31;
    const int w    = tid >> 5;

    #pragma unroll
    for (int q = 0; q < 2; q++) {
        int j = q * 256 + tid;
        s_sa[j] = sa_in[b * SS + j];
        s_sb[j] = sb_in[b * SS + j];
    }
    if (tid < 128) s_w1[tid] = w1[tid];
    else           s_w2[tid - 128] = w2[tid - 128];
    __syncthreads();

    if (w >= 4) {
        // =================== PRODUCER: E + H staging ===================
        const int et = tid - 128;
        const int er = et >> 2;             // row 0..31
        const int eq = et & 3;              // 4 threads/row
        const float sai = s_sa[i0 + er];
        const float sbi = s_sb[i0 + er];
        const unsigned char* crow = g_code + ((size_t)b * SS + i0 + er) * SS;
        const uint32_t* hhiB = hhi_in + (size_t)b * SS * (HH / 2);
        float esum = 0.0f;

        for (int kc = 0; kc < 8; kc++) {
            const int buf = kc & 1;
            if (kc >= 2) BAR_SYNC(3 + buf);

            // stage H(kc): 64 k-rows x 256B fp16
            {
                const uint32_t hb = su + OFF_H + buf * H_BUFSZ;
                #pragma unroll
                for (int t = 0; t < 8; t++) {
                    const int idx = t * 128 + et;
                    const int k = idx >> 4, g = idx & 15;
                    cp16(hb + k * LDHB + g * 16,
                         hhiB + (size_t)(kc * 64 + k) * 64 + g * 4);
                }
                CP_COMMIT();
            }

            // compute E(kc): 2 segs of 8 elems per thread
            {
                char* ph = smem + OFF_P + buf * P_BUFSZ + er * 128;
                #pragma unroll
                for (int u = 0; u < 2; u++) {
                    const int seg = eq * 2 + u;
                    const int j0 = kc * 64 + seg * 8;
                    const ull codes = *(const ull*)(crow + j0);
                    const float4 sb0 = *(const float4*)(s_sb + j0);
                    const float4 sb1 = *(const float4*)(s_sb + j0 + 4);
                    const float4 sa0 = *(const float4*)(s_sa + j0);
                    const float4 sa1 = *(const float4*)(s_sa + j0 + 4);
                    uint32_t h0, h1, h2, h3;
                    esum += quad4((uint32_t)codes,         sa0, sb0, sai, sbi, h0, h1);
                    esum += quad4((uint32_t)(codes >> 32), sa1, sb1, sai, sbi, h2, h3);
                    const uint32_t phys = ((uint32_t)(seg ^ (er & 7))) * 16u;
                    *(uint4*)(ph + phys) = make_uint4(h0, h1, h2, h3);
                }
            }

            CP_WAIT0();
            BAR_ARRIVE(1 + buf);
        }

        esum += __shfl_xor_sync(0xFFFFFFFFu, esum, 1);
        esum += __shfl_xor_sync(0xFFFFFFFFu, esum, 2);
        if (eq == 0) s_rsum[er] = esum;
        BAR_SYNC(5);
    } else {
        // =================== CONSUMER: MMA + epilogue ===================
        const int mi = w & 1;               // 2 M tiles of 16 rows
        const int ni = w >> 1;              // 2 N halves of 64 cols
        const int m0 = mi * 16;
        const int arow = m0 + (lane & 15);
        const int aunit0 = (lane >> 4);
        const int brow = (lane & 7) + ((lane >> 3) & 1) * 8;
        const uint32_t b_cb0 = (uint32_t)(ni * 128 + (lane >> 4) * 16);

        float acc[8][4];
        #pragma unroll
        for (int nf = 0; nf < 8; nf++)
            #pragma unroll
            for (int q = 0; q < 4; q++) acc[nf][q] = 0.0f;

        for (int kc = 0; kc < 8; kc++) {
            const int buf = kc & 1;
            BAR_SYNC(1 + buf);

            const uint32_t pb = su + OFF_P + buf * P_BUFSZ + arow * 128;
            const uint32_t hb = su + OFF_H + buf * H_BUFSZ;
            #pragma unroll
            for (int s = 0; s < 4; s++) {
                const uint32_t phys = (((uint32_t)(s * 2 + aunit0)) ^ (uint32_t)(arow & 7)) * 16u;
                uint32_t a[4];
                ldsm_x4(a, pb + phys);
                const uint32_t brbase = hb + (uint32_t)((s * 16 + brow) * LDHB) + b_cb0;
                #pragma unroll
                for (int nn = 0; nn < 4; nn++) {
                    uint32_t bh[4];
                    ldsm_x4_t(bh, brbase + (uint32_t)(nn * 32));
                    mma16816h(acc[2 * nn],     a, bh[0], bh[1]);
                    mma16816h(acc[2 * nn + 1], a, bh[2], bh[3]);
                }
            }

            if (kc < 6) BAR_ARRIVE(3 + buf);
        }

        BAR_SYNC(5);                                 // rsum ready

        const int r0 = m0 + (lane >> 2);
        const float inv0 = 1.0f / s_rsum[r0];
        const float inv1 = 1.0f / s_rsum[r0 + 8];
        const size_t gr0 = ((size_t)b * SS + i0 + r0) * HH;
        const size_t gr1 = gr0 + 8 * HH;

        if (mode) {
            // layer 1: write fp16 H + partial next-layer sa/sb (cross-warp add)
            float d1a = 0.0f, d2a = 0.0f, d1b = 0.0f, d2b = 0.0f;
            #pragma unroll
            for (int nf = 0; nf < 8; nf++) {
                const int col = ni * 64 + nf * 8 + 2 * (lane & 3);
                const float v0 = acc[nf][0] * inv0, v1 = acc[nf][1] * inv0;
                const float v2 = acc[nf][2] * inv1, v3 = acc[nf][3] * inv1;
                const float wa0 = s_w1[col], wa1 = s_w1[col + 1];
                const float wb0 = s_w2[col], wb1 = s_w2[col + 1];
                d1a += wa0 * v0 + wa1 * v1;  d2a += wb0 * v0 + wb1 * v1;
                d1b += wa0 * v2 + wa1 * v3;  d2b += wb0 * v2 + wb1 * v3;
                hhi_out[(gr0 + col) >> 1] = f2h2(v1, v0);
                hhi_out[(gr1 + col) >> 1] = f2h2(v3, v2);
            }
            #pragma unroll
            for (int off = 1; off <= 2; off <<= 1) {
                d1a += __shfl_xor_sync(0xFFFFFFFFu, d1a, off);
                d2a += __shfl_xor_sync(0xFFFFFFFFu, d2a, off);
                d1b += __shfl_xor_sync(0xFFFFFFFFu, d1b, off);
                d2b += __shfl_xor_sync(0xFFFFFFFFu, d2b, off);
            }
            if (ni == 1 && (lane & 3) == 0) {
                s_red[r0 * 2]           = d1a;
                s_red[r0 * 2 + 1]       = d2a;
                s_red[(r0 + 8) * 2]     = d1b;
                s_red[(r0 + 8) * 2 + 1] = d2b;
            }
            BAR_SYNC_C(6);
            if (ni == 0 && (lane & 3) == 0) {
                const float bias = bias_ptr[0];
                sa_out[b * SS + i0 + r0] = d1a + s_red[r0 * 2] + bias;
                sb_out[b * SS + i0 + r0] = d2a + s_red[r0 * 2 + 1];
                sa_out[b * SS + i0 + r0 + 8] = d1b + s_red[(r0 + 8) * 2] + bias;
                sb_out[b * SS + i0 + r0 + 8] = d2b + s_red[(r0 + 8) * 2 + 1];
            }
        } else {
            // layer 2: write fp32 only
            #pragma unroll
            for (int nf = 0; nf < 8; nf++) {
                const int col = ni * 64 + nf * 8 + 2 * (lane & 3);
                *(float2*)(hout + gr0 + col) =
                    make_float2(acc[nf][0] * inv0, acc[nf][1] * inv0);
                *(float2*)(hout + gr1 + col) =
                    make_float2(acc[nf][2] * inv1, acc[nf][3] * inv1);
            }
        }
    }
}

// ---------------------------------------------------------------
// Kernel 4: gather rows by alias_inputs
// ---------------------------------------------------------------
__global__ void gather_kernel(const float* __restrict__ hfin,
                              const int* __restrict__ alias,
                              float* __restrict__ out) {
    const int tid = blockIdx.x * blockDim.x + threadIdx.x;
    const int N4 = BB * SS * (HH / 4);
    if (tid >= N4) return;
    const int c4 = tid & 31;
    const int s  = (tid >> 5) & (SS - 1);
    const int b  = tid >> (5 + 9);
    const int a  = alias[b * SS + s];
    reinterpret_cast<float4*>(out)[tid] =
        reinterpret_cast<const float4*>(hfin)[((size_t)b * SS + a) * 32 + c4];
}

// ---------------------------------------------------------------
extern "C" void kernel_launch(void* const* d_in, const int* in_sizes, int n_in,
                              void* d_out, int out_size) {
    const float* hidden = (const float*)d_in[0];
    const float* adj    = (const float*)d_in[1];
    const int*   alias  = (const int*)d_in[2];
    const float* w1     = (const float*)d_in[3];
    const float* w2     = (const float*)d_in[4];
    const float* bias   = (const float*)d_in[5];
    float* out = (float*)d_out;

    cudaFuncSetAttribute(fused_layer_kernel,
                         cudaFuncAttributeMaxDynamicSharedMemorySize, SMEM_TOTAL);

    float* hb1;  cudaGetSymbolAddress((void**)&hb1, g_hbuf1);
    uint32_t* hhi; cudaGetSymbolAddress((void**)&hhi, g_hhi);
    float* sav; cudaGetSymbolAddress((void**)&sav, g_sav);
    float* sbv; cudaGetSymbolAddress((void**)&sbv, g_sbv);
    const size_t HC = (size_t)BB * SS * HH / 2;
    const size_t SC = (size_t)BB * SS;

    pack_code_kernel<<<dim3(NPAIR64, 1, BB), 256>>>(adj);

    sasb_split_kernel<<<(BB * SS) / 8, 256>>>(hidden, w1, w2, bias, hhi, sav, sbv);

    // layer 1: reads fp16 H slot0 + sa/sb0; writes fp16 H slot1 + sa/sb1
    fused_layer_kernel<<<dim3(SS / 32, BB), 256, SMEM_TOTAL>>>(
        hhi, sav, sbv, hb1, hhi + HC, sav + SC, sbv + SC, w1, w2, bias, 1);

    // layer 2: reads fp16 H slot1 + sa/sb1; writes fp32 hb1
    fused_layer_kernel<<<dim3(SS / 32, BB), 256, SMEM_TOTAL>>>(
        hhi + HC, sav + SC, sbv + SC, hb1, hhi, sav, sbv, w1, w2, bias, 0);

    const int N4 = BB * SS * (HH / 4);
    gather_kernel<<<(N4 + 255) / 256, 256>>>(hb1, alias, out);
}

// round 16
// speedup vs baseline: 1.0632x; 1.0632x over previous
#include <cuda_runtime.h>
#include <cuda_bf16.h>
#include <cuda_fp16.h>
#include <cstdint>

typedef unsigned long long ull;

#define BB 128
#define SS 512
#define HH 128
#define EPSM 5.9604644775390625e-08f   // 2^-24, exact fp16 subnormal

// -------- static device scratch --------
static __device__ unsigned char g_code[(size_t)BB * SS * SS];
static __device__ float g_hbuf1[(size_t)BB * SS * HH];
static __device__ uint32_t g_hhi[2][(size_t)BB * SS * HH / 2];  // f16x2 pairs
static __device__ float g_sav[2][BB * SS];
static __device__ float g_sbv[2][BB * SS];

// ---------------- fast math ----------------
__device__ __forceinline__ float tanha(float x) {
    float r; asm("tanh.approx.f32 %0,%1;" : "=f"(r) : "f"(x)); return r;
}
__device__ __forceinline__ float ex2a(float x) {
    float r; asm("ex2.approx.f32 %0,%1;" : "=f"(r) : "f"(x)); return r;
}
__device__ __forceinline__ uint32_t f2h2(float hi, float lo) {
    uint32_t r; asm("cvt.rn.f16x2.f32 %0,%1,%2;" : "=r"(r) : "f"(hi), "f"(lo)); return r;
}

// ---------------- mma / ldsm / cp.async / named barriers ----------------
__device__ __forceinline__ void ldsm_x4(uint32_t r[4], uint32_t addr) {
    asm volatile("ldmatrix.sync.aligned.m8n8.x4.shared.b16 {%0,%1,%2,%3}, [%4];"
        : "=r"(r[0]), "=r"(r[1]), "=r"(r[2]), "=r"(r[3]) : "r"(addr));
}
__device__ __forceinline__ void ldsm_x4_t(uint32_t r[4], uint32_t addr) {
    asm volatile("ldmatrix.sync.aligned.m8n8.x4.trans.shared.b16 {%0,%1,%2,%3}, [%4];"
        : "=r"(r[0]), "=r"(r[1]), "=r"(r[2]), "=r"(r[3]) : "r"(addr));
}
__device__ __forceinline__ void mma16816h(float acc[4], const uint32_t a[4],
                                          uint32_t b0, uint32_t b1) {
    asm volatile(
        "mma.sync.aligned.m16n8k16.row.col.f32.f16.f16.f32 "
        "{%0,%1,%2,%3}, {%4,%5,%6,%7}, {%8,%9}, {%0,%1,%2,%3};\n"
        : "+f"(acc[0]), "+f"(acc[1]), "+f"(acc[2]), "+f"(acc[3])
        : "r"(a[0]), "r"(a[1]), "r"(a[2]), "r"(a[3]), "r"(b0), "r"(b1));
}
__device__ __forceinline__ void cp16(uint32_t dst, const void* src) {
    asm volatile("cp.async.cg.shared.global [%0], [%1], 16;" :: "r"(dst), "l"(src));
}
#define CP_COMMIT() asm volatile("cp.async.commit_group;" ::: "memory")
#define CP_WAIT0()  asm volatile("cp.async.wait_group 0;" ::: "memory")
#define BAR_SYNC(id)   asm volatile("bar.sync %0, 256;"   :: "r"(id) : "memory")
#define BAR_ARRIVE(id) asm volatile("bar.arrive %0, 256;" :: "r"(id) : "memory")

// ---------------------------------------------------------------
// Kernel 1: symmetric pack, 64x64 pair-tiles, float4 loads
// ---------------------------------------------------------------
#define NT64 (SS / 64)
#define NPAIR64 (NT64 * (NT64 + 1) / 2)

__global__ __launch_bounds__(256) void pack_code_kernel(const float* __restrict__ adj) {
    __shared__ float tA[64][65], tB[64][65];
    const int b = blockIdx.z;
    int rem = blockIdx.x;
    int It = 0;
    while (rem >= NT64 - It) { rem -= NT64 - It; It++; }
    const int I = It * 64;
    const int J = (It + rem) * 64;
    const int tid = threadIdx.x;
    const float* A = adj + (size_t)b * SS * SS;

    #pragma unroll
    for (int t = 0; t < 4; t++) {
        const int idx = t * 256 + tid;
        const int r = idx >> 4, c4 = idx & 15;
        const float4 va = *(const float4*)(A + (size_t)(I + r) * SS + J + c4 * 4);
        const float4 vb = *(const float4*)(A + (size_t)(J + r) * SS + I + c4 * 4);
        tA[r][c4 * 4 + 0] = va.x; tA[r][c4 * 4 + 1] = va.y;
        tA[r][c4 * 4 + 2] = va.z; tA[r][c4 * 4 + 3] = va.w;
        tB[r][c4 * 4 + 0] = vb.x; tB[r][c4 * 4 + 1] = vb.y;
        tB[r][c4 * 4 + 2] = vb.z; tB[r][c4 * 4 + 3] = vb.w;
    }
    __syncthreads();

    #pragma unroll
    for (int t = 0; t < 4; t++) {
        const int idx = t * 256 + tid;
        const int r = idx >> 4, c4 = idx & 15;
        unsigned char e0[4], e1[4];
        #pragma unroll
        for (int e = 0; e < 4; e++) {
            const int c = c4 * 4 + e;
            e0[e] = (tA[r][c] == 1.0f ? 1u : 0u) | (tB[c][r] == 1.0f ? 2u : 0u);
            e1[e] = (tB[r][c] == 1.0f ? 1u : 0u) | (tA[c][r] == 1.0f ? 2u : 0u);
        }
        *(uchar4*)(g_code + ((size_t)b * SS + I + r) * SS + J + c4 * 4) =
            make_uchar4(e0[0], e0[1], e0[2], e0[3]);
        *(uchar4*)(g_code + ((size_t)b * SS + J + r) * SS + I + c4 * 4) =
            make_uchar4(e1[0], e1[1], e1[2], e1[3]);
    }
}

// ---------------------------------------------------------------
// Kernel 2: sa/sb projections + single-fp16 pack of input hidden
// ---------------------------------------------------------------
__global__ void sasb_split_kernel(const float* __restrict__ hin,
                                  const float* __restrict__ w1,
                                  const float* __restrict__ w2,
                                  const float* __restrict__ bias_ptr,
                                  uint32_t* __restrict__ hi_out,
                                  float* __restrict__ sa_out,
                                  float* __restrict__ sb_out) {
    const int tid  = threadIdx.x;
    const int lane = tid & 31;
    const int row  = blockIdx.x * 8 + (tid >> 5);
    if (row >= BB * SS) return;

    const float4 hv  = reinterpret_cast<const float4*>(hin)[(size_t)row * 32 + lane];
    const float4 w1v = reinterpret_cast<const float4*>(w1)[lane];
    const float4 w2v = reinterpret_cast<const float4*>(w2)[lane];

    reinterpret_cast<uint2*>(hi_out)[(size_t)row * 32 + lane] =
        make_uint2(f2h2(hv.y, hv.x), f2h2(hv.w, hv.z));

    float d1 = hv.x * w1v.x + hv.y * w1v.y + hv.z * w1v.z + hv.w * w1v.w;
    float d2 = hv.x * w2v.x + hv.y * w2v.y + hv.z * w2v.z + hv.w * w2v.w;
    #pragma unroll
    for (int off = 16; off > 0; off >>= 1) {
        d1 += __shfl_xor_sync(0xFFFFFFFFu, d1, off);
        d2 += __shfl_xor_sync(0xFFFFFFFFu, d2, off);
    }
    if (lane == 0) {
        sa_out[row] = d1 + bias_ptr[0];
        sb_out[row] = d2;
    }
}

// ---------------------------------------------------------------
// score quad (MUFU) -> single fp16 P
// ---------------------------------------------------------------
#define HLOG2E 0.721347520444f

__device__ __forceinline__ float quad4(uint32_t c4, const float4 sa4, const float4 sb4,
                                       const float sai, const float sbi,
                                       uint32_t& h01, uint32_t& h23) {
    float t1[4], t2[4];
    t1[0] = tanha(sai + sb4.x);  t1[1] = tanha(sai + sb4.y);
    t1[2] = tanha(sai + sb4.z);  t1[3] = tanha(sai + sb4.w);
    t2[0] = tanha(sa4.x + sbi);  t2[1] = tanha(sa4.y + sbi);
    t2[2] = tanha(sa4.z + sbi);  t2[3] = tanha(sa4.w + sbi);
    float e[4]; float es = 0.0f;
    #pragma unroll
    for (int k = 0; k < 4; k++) {
        const uint32_t c = (c4 >> (8 * k)) & 0xFFu;
        const float f1 = (c & 1u) ? t1[k] : 0.0f;
        const float f2 = (c & 2u) ? t2[k] : 0.0f;
        const float ev = ex2a((f1 + f2) * HLOG2E);
        e[k] = c ? ev : EPSM;
        es += e[k];
    }
    h01 = f2h2(e[1], e[0]);
    h23 = f2h2(e[3], e[2]);
    return es;
}

// ---------------------------------------------------------------
// Kernel 3: WARP-SPECIALIZED fused, single-fp16 P and H,
// 64 rows/block, 256 thr, occ 2, REGISTER-PREFETCHED codes.
// ---------------------------------------------------------------
#define OFF_SA   0
#define OFF_SB   2048
#define OFF_RS   4096
#define OFF_W1   4352
#define OFF_W2   4864
#define OFF_P    5376
#define P_BUFSZ  8192
#define OFF_H    21760
#define H_BUFSZ  17408
#define SMEM_TOTAL 56576
#define LDHB 272

__global__ __launch_bounds__(256, 2)
void fused_layer_kernel(const uint32_t* __restrict__ hhi_in,
                        const float* __restrict__ sa_in,
                        const float* __restrict__ sb_in,
                        float* __restrict__ hout,
                        uint32_t* __restrict__ hhi_out,
                        float* __restrict__ sa_out,
                        float* __restrict__ sb_out,
                        const float* __restrict__ w1,
                        const float* __restrict__ w2,
                        const float* __restrict__ bias_ptr,
                        int mode) {
    extern __shared__ char smem[];
    float* s_sa   = (float*)(smem + OFF_SA);
    float* s_sb   = (float*)(smem + OFF_SB);
    float* s_rsum = (float*)(smem + OFF_RS);
    float* s_w1   = (float*)(smem + OFF_W1);
    float* s_w2   = (float*)(smem + OFF_W2);
    const uint32_t su = (uint32_t)__cvta_generic_to_shared(smem);

    const int b    = blockIdx.y;
    const int i0   = blockIdx.x * 64;
    const int tid  = threadIdx.x;
    const int lane = tid & 31;
    const int w    = tid >> 5;

    #pragma unroll
    for (int q = 0; q < 2; q++) {
        int j = q * 256 + tid;
        s_sa[j] = sa_in[b * SS + j];
        s_sb[j] = sb_in[b * SS + j];
    }
    if (tid < 128) s_w1[tid] = w1[tid];
    else           s_w2[tid - 128] = w2[tid - 128];
    __syncthreads();

    if (w >= 4) {
        // =================== PRODUCER: E + H staging ===================
        const int et = tid - 128;
        const int er = et >> 1;             // row 0..63
        const int eq = et & 1;
        const float sai = s_sa[i0 + er];
        const float sbi = s_sb[i0 + er];
        const unsigned char* crow = g_code + ((size_t)b * SS + i0 + er) * SS;
        const uint32_t* hhiB = hhi_in + (size_t)b * SS * (HH / 2);
        float esum = 0.0f;

        // prologue: prefetch codes for chunk 0
        ull codes_cur[4];
        #pragma unroll
        for (int u = 0; u < 4; u++)
            codes_cur[u] = *(const ull*)(crow + (eq * 4 + u) * 8);

        for (int kc = 0; kc < 8; kc++) {
            const int buf = kc & 1;
            if (kc >= 2) BAR_SYNC(3 + buf);

            // stage H(kc): 64 rows x 256B fp16
            {
                const uint32_t hb = su + OFF_H + buf * H_BUFSZ;
                #pragma unroll
                for (int t = 0; t < 8; t++) {
                    const int idx = t * 128 + et;
                    const int k = idx >> 4, g = idx & 15;
                    cp16(hb + k * LDHB + g * 16,
                         hhiB + (size_t)(kc * 64 + k) * 64 + g * 4);
                }
                CP_COMMIT();
            }

            // prefetch codes for chunk kc+1 (hidden under E(kc))
            ull codes_next[4];
            if (kc < 7) {
                #pragma unroll
                for (int u = 0; u < 4; u++)
                    codes_next[u] = *(const ull*)(crow + (kc + 1) * 64 + (eq * 4 + u) * 8);
            }

            // compute E(kc) from prefetched codes
            {
                char* ph = smem + OFF_P + buf * P_BUFSZ + er * 128;
                #pragma unroll
                for (int u = 0; u < 4; u++) {
                    const int seg = eq * 4 + u;
                    const int j0 = kc * 64 + seg * 8;
                    const ull codes = codes_cur[u];
                    const float4 sb0 = *(const float4*)(s_sb + j0);
                    const float4 sb1 = *(const float4*)(s_sb + j0 + 4);
                    const float4 sa0 = *(const float4*)(s_sa + j0);
                    const float4 sa1 = *(const float4*)(s_sa + j0 + 4);
                    uint32_t h0, h1, h2, h3;
                    esum += quad4((uint32_t)codes,         sa0, sb0, sai, sbi, h0, h1);
                    esum += quad4((uint32_t)(codes >> 32), sa1, sb1, sai, sbi, h2, h3);
                    const uint32_t phys = ((uint32_t)(seg ^ (er & 7))) * 16u;
                    *(uint4*)(ph + phys) = make_uint4(h0, h1, h2, h3);
                }
            }

            if (kc < 7) {
                #pragma unroll
                for (int u = 0; u < 4; u++) codes_cur[u] = codes_next[u];
            }

            CP_WAIT0();
            BAR_ARRIVE(1 + buf);
        }

        esum += __shfl_xor_sync(0xFFFFFFFFu, esum, 1);
        if (eq == 0) s_rsum[er] = esum;
        BAR_SYNC(5);
    } else {
        // =================== CONSUMER: MMA + epilogue ===================
        const int m0 = w * 16;
        const int arow = m0 + (lane & 15);
        const int aunit0 = (lane >> 4);
        const int brow = (lane & 7) + ((lane >> 3) & 1) * 8;
        const uint32_t b_cb0 = (uint32_t)(((lane >> 4) * 8) * 2);

        float acc[16][4];
        #pragma unroll
        for (int nf = 0; nf < 16; nf++)
            #pragma unroll
            for (int q = 0; q < 4; q++) acc[nf][q] = 0.0f;

        for (int kc = 0; kc < 8; kc++) {
            const int buf = kc & 1;
            BAR_SYNC(1 + buf);

            const uint32_t pb = su + OFF_P + buf * P_BUFSZ + arow * 128;
            const uint32_t hb = su + OFF_H + buf * H_BUFSZ;
            #pragma unroll
            for (int s = 0; s < 4; s++) {
                const uint32_t phys = (((uint32_t)(s * 2 + aunit0)) ^ (uint32_t)(arow & 7)) * 16u;
                uint32_t a[4];
                ldsm_x4(a, pb + phys);
                const uint32_t brbase = hb + (uint32_t)((s * 16 + brow) * LDHB) + b_cb0;
                #pragma unroll
                for (int nn = 0; nn < 8; nn++) {
                    uint32_t bh[4];
                    ldsm_x4_t(bh, brbase + (uint32_t)(nn * 32));
                    mma16816h(acc[2 * nn],     a, bh[0], bh[1]);
                    mma16816h(acc[2 * nn + 1], a, bh[2], bh[3]);
                }
            }

            if (kc < 6) BAR_ARRIVE(3 + buf);
        }

        BAR_SYNC(5);                                 // rsum ready

        const int r0 = m0 + (lane >> 2);
        const float inv0 = 1.0f / s_rsum[r0];
        const float inv1 = 1.0f / s_rsum[r0 + 8];
        const size_t gr0 = ((size_t)b * SS + i0 + r0) * HH;
        const size_t gr1 = gr0 + 8 * HH;

        if (mode) {
            // layer 1: write fp16 H + accumulate next-layer sa/sb
            float d1a = 0.0f, d2a = 0.0f, d1b = 0.0f, d2b = 0.0f;
            #pragma unroll
            for (int nf = 0; nf < 16; nf++) {
                const int col = nf * 8 + 2 * (lane & 3);
                const float v0 = acc[nf][0] * inv0, v1 = acc[nf][1] * inv0;
                const float v2 = acc[nf][2] * inv1, v3 = acc[nf][3] * inv1;
                const float wa0 = s_w1[col], wa1 = s_w1[col + 1];
                const float wb0 = s_w2[col], wb1 = s_w2[col + 1];
                d1a += wa0 * v0 + wa1 * v1;  d2a += wb0 * v0 + wb1 * v1;
                d1b += wa0 * v2 + wa1 * v3;  d2b += wb0 * v2 + wb1 * v3;
                hhi_out[(gr0 + col) >> 1] = f2h2(v1, v0);
                hhi_out[(gr1 + col) >> 1] = f2h2(v3, v2);
            }
            #pragma unroll
            for (int off = 1; off <= 2; off <<= 1) {
                d1a += __shfl_xor_sync(0xFFFFFFFFu, d1a, off);
                d2a += __shfl_xor_sync(0xFFFFFFFFu, d2a, off);
                d1b += __shfl_xor_sync(0xFFFFFFFFu, d1b, off);
                d2b += __shfl_xor_sync(0xFFFFFFFFu, d2b, off);
            }
            if ((lane & 3) == 0) {
                const float bias = bias_ptr[0];
                sa_out[b * SS + i0 + r0] = d1a + bias;
                sb_out[b * SS + i0 + r0] = d2a;
                sa_out[b * SS + i0 + r0 + 8] = d1b + bias;
                sb_out[b * SS + i0 + r0 + 8] = d2b;
            }
        } else {
            // layer 2: write fp32 only
            #pragma unroll
            for (int nf = 0; nf < 16; nf++) {
                const int col = nf * 8 + 2 * (lane & 3);
                *(float2*)(hout + gr0 + col) =
                    make_float2(acc[nf][0] * inv0, acc[nf][1] * inv0);
                *(float2*)(hout + gr1 + col) =
                    make_float2(acc[nf][2] * inv1, acc[nf][3] * inv1);
            }
        }
    }
}

// ---------------------------------------------------------------
// Kernel 4: gather rows by alias_inputs
// ---------------------------------------------------------------
__global__ void gather_kernel(const float* __restrict__ hfin,
                              const int* __restrict__ alias,
                              float* __restrict__ out) {
    const int tid = blockIdx.x * blockDim.x + threadIdx.x;
    const int N4 = BB * SS * (HH / 4);
    if (tid >= N4) return;
    const int c4 = tid & 31;
    const int s  = (tid >> 5) & (SS - 1);
    const int b  = tid >> (5 + 9);
    const int a  = alias[b * SS + s];
    reinterpret_cast<float4*>(out)[tid] =
        reinterpret_cast<const float4*>(hfin)[((size_t)b * SS + a) * 32 + c4];
}

// ---------------------------------------------------------------
extern "C" void kernel_launch(void* const* d_in, const int* in_sizes, int n_in,
                              void* d_out, int out_size) {
    const float* hidden = (const float*)d_in[0];
    const float* adj    = (const float*)d_in[1];
    const int*   alias  = (const int*)d_in[2];
    const float* w1     = (const float*)d_in[3];
    const float* w2     = (const float*)d_in[4];
    const float* bias   = (const float*)d_in[5];
    float* out = (float*)d_out;

    cudaFuncSetAttribute(fused_layer_kernel,
                         cudaFuncAttributeMaxDynamicSharedMemorySize, SMEM_TOTAL);

    float* hb1;  cudaGetSymbolAddress((void**)&hb1, g_hbuf1);
    uint32_t* hhi; cudaGetSymbolAddress((void**)&hhi, g_hhi);
    float* sav; cudaGetSymbolAddress((void**)&sav, g_sav);
    float* sbv; cudaGetSymbolAddress((void**)&sbv, g_sbv);
    const size_t HC = (size_t)BB * SS * HH / 2;
    const size_t SC = (size_t)BB * SS;

    pack_code_kernel<<<dim3(NPAIR64, 1, BB), 256>>>(adj);

    sasb_split_kernel<<<(BB * SS) / 8, 256>>>(hidden, w1, w2, bias, hhi, sav, sbv);

    // layer 1: reads fp16 H slot0 + sa/sb0; writes fp16 H slot1 + sa/sb1
    fused_layer_kernel<<<dim3(SS / 64, BB), 256, SMEM_TOTAL>>>(
        hhi, sav, sbv, hb1, hhi + HC, sav + SC, sbv + SC, w1, w2, bias, 1);

    // layer 2: reads fp16 H slot1 + sa/sb1; writes fp32 hb1
    fused_layer_kernel<<<dim3(SS / 64, BB), 256, SMEM_TOTAL>>>(
        hhi + HC, sav + SC, sbv + SC, hb1, hhi, sav, sbv, w1, w2, bias, 0);

    const int N4 = BB * SS * (HH / 4);
    gather_kernel<<<(N4 + 255) / 256, 256>>>(hb1, alias, out);
}